// round 9
// baseline (speedup 1.0000x reference)
#include <cuda_runtime.h>

// SphereDownGeo: y[c,k] = sum_d M_vals[k,d] * x[c, M_cols[k,d]]
// M_cols[k,d] = clip(4k + off, 0, N-1), off in [-6,10).
//
// 2 outputs per thread: k_a = k0+2t, k_b = k0+2t+1 share a 6-float4 window
// (floats [8t, 8t+24) of the block window). Dense weights built by an
// in-register select network (R8, proven). Window float4s stored/read with
// involutive swizzle p = i ^ ((i>>3)&7) so the stride-2-float4 lane pattern
// hits the 4-wavefront LDS.128 floor. float2 stores.

#define KPB    128                 // threads per block
#define KBLK   256                 // k's per block (2 per thread)
#define DEG    16
#define CCH    8
#define SEGV   260                 // float4s per channel window (1040 floats)
#define NV4    (CCH * SEGV)        // 2080 total float4s (multiple of 8)

#define SWZ(i) ((i) ^ (((i) >> 3) & 7))

#define ROUTE16(p, j, v)                                        \
    do { int _j = (j); float _v = (v);                          \
        p##0 += (_j == 0 ) ? _v : 0.0f;                         \
        p##1 += (_j == 1 ) ? _v : 0.0f;                         \
        p##2 += (_j == 2 ) ? _v : 0.0f;                         \
        p##3 += (_j == 3 ) ? _v : 0.0f;                         \
        p##4 += (_j == 4 ) ? _v : 0.0f;                         \
        p##5 += (_j == 5 ) ? _v : 0.0f;                         \
        p##6 += (_j == 6 ) ? _v : 0.0f;                         \
        p##7 += (_j == 7 ) ? _v : 0.0f;                         \
        p##8 += (_j == 8 ) ? _v : 0.0f;                         \
        p##9 += (_j == 9 ) ? _v : 0.0f;                         \
        p##A += (_j == 10) ? _v : 0.0f;                         \
        p##B += (_j == 11) ? _v : 0.0f;                         \
        p##C += (_j == 12) ? _v : 0.0f;                         \
        p##D += (_j == 13) ? _v : 0.0f;                         \
        p##E += (_j == 14) ? _v : 0.0f;                         \
        p##F += (_j == 15) ? _v : 0.0f;                         \
    } while (0)

#define DECL16(p)                                               \
    float p##0 = 0.f, p##1 = 0.f, p##2 = 0.f, p##3 = 0.f;       \
    float p##4 = 0.f, p##5 = 0.f, p##6 = 0.f, p##7 = 0.f;       \
    float p##8 = 0.f, p##9 = 0.f, p##A = 0.f, p##B = 0.f;       \
    float p##C = 0.f, p##D = 0.f, p##E = 0.f, p##F = 0.f;

__global__ __launch_bounds__(KPB)
void sphere_down_kernel(const float*  __restrict__ x,
                        const int*    __restrict__ M_cols,
                        const float*  __restrict__ M_vals,
                        const int*    __restrict__ cell_ids,
                        float*        __restrict__ out,
                        int n_in, int k_out)
{
    __shared__ __align__(16) float4 xs4[NV4];

    const int k0 = blockIdx.x * KBLK;
    const int t  = threadIdx.x;
    const int ka = k0 + 2 * t;          // first output

    const int vbase = k0 - 2;           // float4 window base: float idx 4*k0-8
    const int nv    = n_in >> 2;        // N_IN % 4 == 0

    // ---- Stage x window (LDG.128 -> swizzled STS.128, zero-fill OOB) ----
    const float4* __restrict__ x4 = (const float4*)x;
    for (int jj = t; jj < NV4; jj += KPB) {
        int c = jj / SEGV;
        int i = jj - c * SEGV;
        int v = vbase + i;
        float4 val = make_float4(0.f, 0.f, 0.f, 0.f);
        if ((unsigned)v < (unsigned)nv)
            val = x4[(size_t)c * nv + v];
        xs4[SWZ(jj)] = val;
    }

    // ---- Route dense weights for both k's (overlaps staging latency) ----
    DECL16(wa)
    DECL16(wb)
    {
        const int4*   cpa = (const int4*)(M_cols + (size_t)ka * DEG);
        const float4* vpa = (const float4*)(M_vals + (size_t)ka * DEG);
        const int jra = 4 * ka - 6;
        #pragma unroll
        for (int i = 0; i < 4; i++) {
            int4   c4 = cpa[i];
            float4 v4 = vpa[i];
            ROUTE16(wa, c4.x - jra, v4.x);  ROUTE16(wa, c4.y - jra, v4.y);
            ROUTE16(wa, c4.z - jra, v4.z);  ROUTE16(wa, c4.w - jra, v4.w);
        }
        const int4*   cpb = cpa + 4;    // row ka+1
        const float4* vpb = vpa + 4;
        const int jrb = jra + 4;        // 4*(ka+1) - 6
        #pragma unroll
        for (int i = 0; i < 4; i++) {
            int4   c4 = cpb[i];
            float4 v4 = vpb[i];
            ROUTE16(wb, c4.x - jrb, v4.x);  ROUTE16(wb, c4.y - jrb, v4.y);
            ROUTE16(wb, c4.z - jrb, v4.z);  ROUTE16(wb, c4.w - jrb, v4.w);
        }
    }

    __syncthreads();

    // ---- Per channel: 6 swizzled LDS.128 (floats [8t, 8t+24)), 32 FMAs,
    //      one float2 store covering both outputs ----
    #pragma unroll
    for (int c = 0; c < CCH; c++) {
        const int base = c * SEGV + 2 * t;
        float4 f0 = xs4[SWZ(base + 0)];
        float4 f1 = xs4[SWZ(base + 1)];
        float4 f2 = xs4[SWZ(base + 2)];
        float4 f3 = xs4[SWZ(base + 3)];
        float4 f4 = xs4[SWZ(base + 4)];
        float4 f5 = xs4[SWZ(base + 5)];

        // k_a: weight j multiplies window float (8t+2+j) -> f[(2+j)/4]
        float a0 = wa0 * f0.z;
        float a1 = wa1 * f0.w;
        a0 = fmaf(wa2, f1.x, a0);  a1 = fmaf(wa3, f1.y, a1);
        a0 = fmaf(wa4, f1.z, a0);  a1 = fmaf(wa5, f1.w, a1);
        a0 = fmaf(wa6, f2.x, a0);  a1 = fmaf(wa7, f2.y, a1);
        a0 = fmaf(wa8, f2.z, a0);  a1 = fmaf(wa9, f2.w, a1);
        a0 = fmaf(waA, f3.x, a0);  a1 = fmaf(waB, f3.y, a1);
        a0 = fmaf(waC, f3.z, a0);  a1 = fmaf(waD, f3.w, a1);
        a0 = fmaf(waE, f4.x, a0);  a1 = fmaf(waF, f4.y, a1);

        // k_b: weight j multiplies window float (8t+6+j)
        float b0 = wb0 * f1.z;
        float b1 = wb1 * f1.w;
        b0 = fmaf(wb2, f2.x, b0);  b1 = fmaf(wb3, f2.y, b1);
        b0 = fmaf(wb4, f2.z, b0);  b1 = fmaf(wb5, f2.w, b1);
        b0 = fmaf(wb6, f3.x, b0);  b1 = fmaf(wb7, f3.y, b1);
        b0 = fmaf(wb8, f3.z, b0);  b1 = fmaf(wb9, f3.w, b1);
        b0 = fmaf(wbA, f4.x, b0);  b1 = fmaf(wbB, f4.y, b1);
        b0 = fmaf(wbC, f4.z, b0);  b1 = fmaf(wbD, f4.w, b1);
        b0 = fmaf(wbE, f5.x, b0);  b1 = fmaf(wbF, f5.y, b1);

        float2 o = make_float2(a0 + a1, b0 + b1);
        *(float2*)(out + (size_t)c * k_out + ka) = o;
    }

    // ---- cell_ids pass-through (second tuple element), float2 ----
    {
        int2 ci = *(const int2*)(cell_ids + ka);
        float2 o = make_float2((float)ci.x, (float)ci.y);
        *(float2*)(out + (size_t)CCH * k_out + ka) = o;
    }
}

extern "C" void kernel_launch(void* const* d_in, const int* in_sizes, int n_in_args,
                              void* d_out, int out_size)
{
    const float* x        = (const float*)d_in[0];   // (1, 8, N_IN) f32
    const int*   M_cols   = (const int*)  d_in[1];   // (K_OUT, 16) i32
    const float* M_vals   = (const float*)d_in[2];   // (K_OUT, 16) f32
    const int*   cell_ids = (const int*)  d_in[3];   // (K_OUT,)    i32

    const int N_IN  = in_sizes[0] / CCH;      // 3,145,728
    const int K_OUT = in_sizes[3];            // 786,432

    float* out = (float*)d_out;

    const int grid = (K_OUT + KBLK - 1) / KBLK;  // 3072, exact
    sphere_down_kernel<<<grid, KPB>>>(x, M_cols, M_vals, cell_ids, out,
                                      N_IN, K_OUT);
}

// round 10
// speedup vs baseline: 1.4359x; 1.4359x over previous
#include <cuda_runtime.h>

// SphereDownGeo: y[c,k] = sum_d M_vals[k,d] * x[c, M_cols[k,d]]
// M_cols[k,d] = clip(4k + off, 0, N-1), off in [-6,10).
//
// Shifted window: smem[s] = x[4*k0 - 6 + s], so thread t's 16 taps (j=0..15)
// occupy floats 4t..4t+15 = float4s t..t+3 exactly. Thread loads only its own
// float4 (F0) + one patch float4 (G); F1..F3 come from warp shuffles with
// lanes 29-31 patched from G. Dense weights via R8's in-register select
// network. Window LDS cost: 8 wf/warp/channel vs R8's 20.

#define KPB    256
#define DEG    16
#define CCH    8
#define SEGF   1040                // window floats per channel
#define SEGV   260                 // window float4s per channel

#define ROUTE16(j, v)                                           \
    do { int _j = (j); float _v = (v);                          \
        w0 += (_j == 0 ) ? _v : 0.0f;                           \
        w1 += (_j == 1 ) ? _v : 0.0f;                           \
        w2 += (_j == 2 ) ? _v : 0.0f;                           \
        w3 += (_j == 3 ) ? _v : 0.0f;                           \
        w4 += (_j == 4 ) ? _v : 0.0f;                           \
        w5 += (_j == 5 ) ? _v : 0.0f;                           \
        w6 += (_j == 6 ) ? _v : 0.0f;                           \
        w7 += (_j == 7 ) ? _v : 0.0f;                           \
        w8 += (_j == 8 ) ? _v : 0.0f;                           \
        w9 += (_j == 9 ) ? _v : 0.0f;                           \
        wA += (_j == 10) ? _v : 0.0f;                           \
        wB += (_j == 11) ? _v : 0.0f;                           \
        wC += (_j == 12) ? _v : 0.0f;                           \
        wD += (_j == 13) ? _v : 0.0f;                           \
        wE += (_j == 14) ? _v : 0.0f;                           \
        wF += (_j == 15) ? _v : 0.0f;                           \
    } while (0)

#define SHFL4_DN(dst, src, d)                                           \
    do { dst.x = __shfl_down_sync(0xffffffffu, src.x, d);               \
         dst.y = __shfl_down_sync(0xffffffffu, src.y, d);               \
         dst.z = __shfl_down_sync(0xffffffffu, src.z, d);               \
         dst.w = __shfl_down_sync(0xffffffffu, src.w, d); } while (0)

#define SHFL4_UP(dst, src, d)                                           \
    do { dst.x = __shfl_up_sync(0xffffffffu, src.x, d);                 \
         dst.y = __shfl_up_sync(0xffffffffu, src.y, d);                 \
         dst.z = __shfl_up_sync(0xffffffffu, src.z, d);                 \
         dst.w = __shfl_up_sync(0xffffffffu, src.w, d); } while (0)

__global__ __launch_bounds__(KPB, 5)
void sphere_down_kernel(const float*  __restrict__ x,
                        const int*    __restrict__ M_cols,
                        const float*  __restrict__ M_vals,
                        const int*    __restrict__ cell_ids,
                        float*        __restrict__ out,
                        int n_in, int k_out)
{
    __shared__ __align__(16) float xsf[CCH * SEGF];
    float4* xs4 = (float4*)xsf;

    const int k0 = blockIdx.x * KPB;
    const int t  = threadIdx.x;
    const int k  = k0 + t;
    const int g0 = 4 * k0 - 6;         // global float of smem[0]

    // ---- Stage shifted window, scalar (contiguous lanes: 1 wf / 128B) ----
    #pragma unroll
    for (int c = 0; c < CCH; c++) {
        const float* xp = x + (size_t)c * n_in;
        #pragma unroll
        for (int m = 0; m < 5; m++) {
            int s = t + m * KPB;
            if (s < SEGF) {
                int g = g0 + s;
                xsf[c * SEGF + s] =
                    ((unsigned)g < (unsigned)n_in) ? xp[g] : 0.0f;
            }
        }
    }

    // ---- Route dense weights (in-register select network, R8-proven) ----
    float w0 = 0.f, w1 = 0.f, w2 = 0.f, w3 = 0.f;
    float w4 = 0.f, w5 = 0.f, w6 = 0.f, w7 = 0.f;
    float w8 = 0.f, w9 = 0.f, wA = 0.f, wB = 0.f;
    float wC = 0.f, wD = 0.f, wE = 0.f, wF = 0.f;
    {
        const int4*   cp = (const int4*)(M_cols + (size_t)k * DEG);
        const float4* vp = (const float4*)(M_vals + (size_t)k * DEG);
        int4   c0 = cp[0], c1 = cp[1], c2 = cp[2], c3 = cp[3];
        float4 v0 = vp[0], v1 = vp[1], v2 = vp[2], v3 = vp[3];
        const int jref = 4 * k - 6;    // j = col - jref, provably in [0,16)
        ROUTE16(c0.x - jref, v0.x);  ROUTE16(c0.y - jref, v0.y);
        ROUTE16(c0.z - jref, v0.z);  ROUTE16(c0.w - jref, v0.w);
        ROUTE16(c1.x - jref, v1.x);  ROUTE16(c1.y - jref, v1.y);
        ROUTE16(c1.z - jref, v1.z);  ROUTE16(c1.w - jref, v1.w);
        ROUTE16(c2.x - jref, v2.x);  ROUTE16(c2.y - jref, v2.y);
        ROUTE16(c2.z - jref, v2.z);  ROUTE16(c2.w - jref, v2.w);
        ROUTE16(c3.x - jref, v3.x);  ROUTE16(c3.y - jref, v3.y);
        ROUTE16(c3.z - jref, v3.z);  ROUTE16(c3.w - jref, v3.w);
    }

    __syncthreads();

    const int lam = t & 31;            // lane
    const int wb  = t & ~31;           // warp's first t
    const bool p1 = (lam <= 30);
    const bool p2 = (lam <= 29);
    const bool p3 = (lam <= 28);

    // ---- Per channel: F0 + patch G (2 LDS.128, 8 wf/warp), shuffles for
    //      F1..F3, 16 FMAs, coalesced scalar store ----
    #pragma unroll
    for (int c = 0; c < CCH; c++) {
        const float4* B = xs4 + c * SEGV;
        float4 F0 = B[t];              // float4 index t   (floats 4t..4t+3)
        float4 G  = B[wb + 3 + lam];   // patch: lane 29->wb+32, 30->wb+33, 31->wb+34

        float4 F1, F2, F3, Gu1, Gu2;
        SHFL4_DN(F1, F0, 1);
        SHFL4_DN(F2, F0, 2);
        SHFL4_DN(F3, F0, 3);
        SHFL4_UP(Gu1, G, 1);
        SHFL4_UP(Gu2, G, 2);

        F1.x = p1 ? F1.x : Gu2.x;  F1.y = p1 ? F1.y : Gu2.y;
        F1.z = p1 ? F1.z : Gu2.z;  F1.w = p1 ? F1.w : Gu2.w;
        F2.x = p2 ? F2.x : Gu1.x;  F2.y = p2 ? F2.y : Gu1.y;
        F2.z = p2 ? F2.z : Gu1.z;  F2.w = p2 ? F2.w : Gu1.w;
        F3.x = p3 ? F3.x : G.x;    F3.y = p3 ? F3.y : G.y;
        F3.z = p3 ? F3.z : G.z;    F3.w = p3 ? F3.w : G.w;

        // tap j multiplies float 4t+j -> F_{j>>2} component j&3
        float a0 = w0 * F0.x;
        float a1 = w1 * F0.y;
        a0 = fmaf(w2, F0.z, a0);  a1 = fmaf(w3, F0.w, a1);
        a0 = fmaf(w4, F1.x, a0);  a1 = fmaf(w5, F1.y, a1);
        a0 = fmaf(w6, F1.z, a0);  a1 = fmaf(w7, F1.w, a1);
        a0 = fmaf(w8, F2.x, a0);  a1 = fmaf(w9, F2.y, a1);
        a0 = fmaf(wA, F2.z, a0);  a1 = fmaf(wB, F2.w, a1);
        a0 = fmaf(wC, F3.x, a0);  a1 = fmaf(wD, F3.y, a1);
        a0 = fmaf(wE, F3.z, a0);  a1 = fmaf(wF, F3.w, a1);

        out[(size_t)c * k_out + k] = a0 + a1;
    }

    // ---- cell_ids pass-through (second tuple element) ----
    out[(size_t)CCH * k_out + k] = (float)cell_ids[k];
}

extern "C" void kernel_launch(void* const* d_in, const int* in_sizes, int n_in_args,
                              void* d_out, int out_size)
{
    const float* x        = (const float*)d_in[0];   // (1, 8, N_IN) f32
    const int*   M_cols   = (const int*)  d_in[1];   // (K_OUT, 16) i32
    const float* M_vals   = (const float*)d_in[2];   // (K_OUT, 16) f32
    const int*   cell_ids = (const int*)  d_in[3];   // (K_OUT,)    i32

    const int N_IN  = in_sizes[0] / CCH;      // 3,145,728
    const int K_OUT = in_sizes[3];            // 786,432

    float* out = (float*)d_out;

    const int grid = (K_OUT + KPB - 1) / KPB; // 3072, exact
    sphere_down_kernel<<<grid, KPB>>>(x, M_cols, M_vals, cell_ids, out,
                                      N_IN, K_OUT);
}

// round 11
// speedup vs baseline: 2.0789x; 1.4478x over previous
#include <cuda_runtime.h>

// SphereDownGeo: y[c,k] = sum_d M_vals[k,d] * x[c, M_cols[k,d]]
// M_cols[k,d] = clip(4k + off, 0, N-1), off in [-6,10).
//
// Direct-global window: thread t's 16 taps occupy floats [4k-6, 4k+10) which
// sit inside the 16B-aligned span [4k-8, 4k+12) = 5 aligned LDG.128. For
// fixed q, consecutive lanes read consecutive float4s -> fully coalesced
// (4 wf/instr); intra-warp 5x line overlap is served by L1. No SMEM, no
// barrier, no staging phase. Dense weights via the R8 in-register select
// network (tap j multiplies window float (j+2) -> P[(j+2)/4].comp[(j+2)%4]).

#define KPB    256
#define DEG    16
#define CCH    8

#define ROUTE16(j, v)                                           \
    do { int _j = (j); float _v = (v);                          \
        w0 += (_j == 0 ) ? _v : 0.0f;                           \
        w1 += (_j == 1 ) ? _v : 0.0f;                           \
        w2 += (_j == 2 ) ? _v : 0.0f;                           \
        w3 += (_j == 3 ) ? _v : 0.0f;                           \
        w4 += (_j == 4 ) ? _v : 0.0f;                           \
        w5 += (_j == 5 ) ? _v : 0.0f;                           \
        w6 += (_j == 6 ) ? _v : 0.0f;                           \
        w7 += (_j == 7 ) ? _v : 0.0f;                           \
        w8 += (_j == 8 ) ? _v : 0.0f;                           \
        w9 += (_j == 9 ) ? _v : 0.0f;                           \
        wA += (_j == 10) ? _v : 0.0f;                           \
        wB += (_j == 11) ? _v : 0.0f;                           \
        wC += (_j == 12) ? _v : 0.0f;                           \
        wD += (_j == 13) ? _v : 0.0f;                           \
        wE += (_j == 14) ? _v : 0.0f;                           \
        wF += (_j == 15) ? _v : 0.0f;                           \
    } while (0)

__global__ __launch_bounds__(KPB)
void sphere_down_kernel(const float*  __restrict__ x,
                        const int*    __restrict__ M_cols,
                        const float*  __restrict__ M_vals,
                        const int*    __restrict__ cell_ids,
                        float*        __restrict__ out,
                        int n_in, int k_out)
{
    const int k  = blockIdx.x * KPB + threadIdx.x;
    const int nv = n_in >> 2;              // N_IN % 4 == 0
    const int vb = k - 2;                  // first float4 index of the span

    // ---- Load cols/vals (vectorized, per-thread row) and route into the
    //      dense 16-weight register network ----
    float w0 = 0.f, w1 = 0.f, w2 = 0.f, w3 = 0.f;
    float w4 = 0.f, w5 = 0.f, w6 = 0.f, w7 = 0.f;
    float w8 = 0.f, w9 = 0.f, wA = 0.f, wB = 0.f;
    float wC = 0.f, wD = 0.f, wE = 0.f, wF = 0.f;
    {
        const int4*   cp = (const int4*)(M_cols + (size_t)k * DEG);
        const float4* vp = (const float4*)(M_vals + (size_t)k * DEG);
        int4   c0 = cp[0], c1 = cp[1], c2 = cp[2], c3 = cp[3];
        float4 v0 = vp[0], v1 = vp[1], v2 = vp[2], v3 = vp[3];
        const int jref = 4 * k - 6;        // j = col - jref, provably in [0,16)
        ROUTE16(c0.x - jref, v0.x);  ROUTE16(c0.y - jref, v0.y);
        ROUTE16(c0.z - jref, v0.z);  ROUTE16(c0.w - jref, v0.w);
        ROUTE16(c1.x - jref, v1.x);  ROUTE16(c1.y - jref, v1.y);
        ROUTE16(c1.z - jref, v1.z);  ROUTE16(c1.w - jref, v1.w);
        ROUTE16(c2.x - jref, v2.x);  ROUTE16(c2.y - jref, v2.y);
        ROUTE16(c2.z - jref, v2.z);  ROUTE16(c2.w - jref, v2.w);
        ROUTE16(c3.x - jref, v3.x);  ROUTE16(c3.y - jref, v3.y);
        ROUTE16(c3.z - jref, v3.z);  ROUTE16(c3.w - jref, v3.w);
    }

    const float4* __restrict__ x4 = (const float4*)x;
    const bool g0 = (unsigned)(vb + 0) < (unsigned)nv;
    const bool g1 = (unsigned)(vb + 1) < (unsigned)nv;
    const bool g2 = (unsigned)(vb + 2) < (unsigned)nv;
    const bool g3 = (unsigned)(vb + 3) < (unsigned)nv;
    const bool g4 = (unsigned)(vb + 4) < (unsigned)nv;
    const float4 Z = make_float4(0.f, 0.f, 0.f, 0.f);

    // ---- Per channel: 5 coalesced aligned LDG.128 + 16 FMAs + store ----
    #pragma unroll
    for (int c = 0; c < CCH; c++) {
        const float4* B = x4 + (size_t)c * nv + vb;
        float4 F0 = g0 ? B[0] : Z;
        float4 F1 = g1 ? B[1] : Z;
        float4 F2 = g2 ? B[2] : Z;
        float4 F3 = g3 ? B[3] : Z;
        float4 F4 = g4 ? B[4] : Z;

        // tap j multiplies window float (4k-8) + (j+2)
        float a0 = w0 * F0.z;
        float a1 = w1 * F0.w;
        a0 = fmaf(w2, F1.x, a0);  a1 = fmaf(w3, F1.y, a1);
        a0 = fmaf(w4, F1.z, a0);  a1 = fmaf(w5, F1.w, a1);
        a0 = fmaf(w6, F2.x, a0);  a1 = fmaf(w7, F2.y, a1);
        a0 = fmaf(w8, F2.z, a0);  a1 = fmaf(w9, F2.w, a1);
        a0 = fmaf(wA, F3.x, a0);  a1 = fmaf(wB, F3.y, a1);
        a0 = fmaf(wC, F3.z, a0);  a1 = fmaf(wD, F3.w, a1);
        a0 = fmaf(wE, F4.x, a0);  a1 = fmaf(wF, F4.y, a1);

        out[(size_t)c * k_out + k] = a0 + a1;
    }

    // ---- cell_ids pass-through (second tuple element) ----
    out[(size_t)CCH * k_out + k] = (float)cell_ids[k];
}

extern "C" void kernel_launch(void* const* d_in, const int* in_sizes, int n_in_args,
                              void* d_out, int out_size)
{
    const float* x        = (const float*)d_in[0];   // (1, 8, N_IN) f32
    const int*   M_cols   = (const int*)  d_in[1];   // (K_OUT, 16) i32
    const float* M_vals   = (const float*)d_in[2];   // (K_OUT, 16) f32
    const int*   cell_ids = (const int*)  d_in[3];   // (K_OUT,)    i32

    const int N_IN  = in_sizes[0] / CCH;      // 3,145,728
    const int K_OUT = in_sizes[3];            // 786,432

    float* out = (float*)d_out;

    const int grid = (K_OUT + KPB - 1) / KPB; // 3072, exact
    sphere_down_kernel<<<grid, KPB>>>(x, M_cols, M_vals, cell_ids, out,
                                      N_IN, K_OUT);
}

// round 12
// speedup vs baseline: 2.2400x; 1.0775x over previous
#include <cuda_runtime.h>

// SphereDownGeo: y[c,k] = sum_d M_vals[k,d] * x[c, M_cols[k,d]]
// M_cols[k,d] = clip(4k + off, 0, N-1), off in [-6,10).
//
// Direct-global window (R11, proven): thread t's 16 taps sit in the aligned
// span [4k-8, 4k+12) = 5 coalesced LDG.128. Dense 16-weight crossbar built
// with inline-asm predicated adds (ISETP + @p FADD = 2 ops per tap-slot,
// the structural floor; removes R11's FSEL third op).

#define KPB    256
#define DEG    16
#define CCH    8

// One guarded add: w += (j == S) ? v : 0, forced to ISETP + @p FADD.
#define RSEL(w, j, v, S)                                                \
    asm("{\n\t.reg .pred p;\n\t"                                        \
        "setp.eq.s32 p, %1, " #S ";\n\t"                                \
        "@p add.f32 %0, %0, %2;\n\t}"                                   \
        : "+f"(w) : "r"(j), "f"(v))

#define ROUTE16(j, v)                                                   \
    do { int _j = (j); float _v = (v);                                  \
        RSEL(w0, _j, _v, 0);   RSEL(w1, _j, _v, 1);                     \
        RSEL(w2, _j, _v, 2);   RSEL(w3, _j, _v, 3);                     \
        RSEL(w4, _j, _v, 4);   RSEL(w5, _j, _v, 5);                     \
        RSEL(w6, _j, _v, 6);   RSEL(w7, _j, _v, 7);                     \
        RSEL(w8, _j, _v, 8);   RSEL(w9, _j, _v, 9);                     \
        RSEL(wA, _j, _v, 10);  RSEL(wB, _j, _v, 11);                    \
        RSEL(wC, _j, _v, 12);  RSEL(wD, _j, _v, 13);                    \
        RSEL(wE, _j, _v, 14);  RSEL(wF, _j, _v, 15);                    \
    } while (0)

__global__ __launch_bounds__(KPB)
void sphere_down_kernel(const float*  __restrict__ x,
                        const int*    __restrict__ M_cols,
                        const float*  __restrict__ M_vals,
                        const int*    __restrict__ cell_ids,
                        float*        __restrict__ out,
                        int n_in, int k_out)
{
    const int k  = blockIdx.x * KPB + threadIdx.x;
    const int nv = n_in >> 2;              // N_IN % 4 == 0
    const int vb = k - 2;                  // first float4 index of the span

    // ---- Load cols/vals (vectorized, per-thread row), route into the
    //      dense 16-weight register crossbar ----
    float w0 = 0.f, w1 = 0.f, w2 = 0.f, w3 = 0.f;
    float w4 = 0.f, w5 = 0.f, w6 = 0.f, w7 = 0.f;
    float w8 = 0.f, w9 = 0.f, wA = 0.f, wB = 0.f;
    float wC = 0.f, wD = 0.f, wE = 0.f, wF = 0.f;
    {
        const int4*   cp = (const int4*)(M_cols + (size_t)k * DEG);
        const float4* vp = (const float4*)(M_vals + (size_t)k * DEG);
        int4   c0 = cp[0], c1 = cp[1], c2 = cp[2], c3 = cp[3];
        float4 v0 = vp[0], v1 = vp[1], v2 = vp[2], v3 = vp[3];
        const int jref = 4 * k - 6;        // j = col - jref, provably in [0,16)
        ROUTE16(c0.x - jref, v0.x);  ROUTE16(c0.y - jref, v0.y);
        ROUTE16(c0.z - jref, v0.z);  ROUTE16(c0.w - jref, v0.w);
        ROUTE16(c1.x - jref, v1.x);  ROUTE16(c1.y - jref, v1.y);
        ROUTE16(c1.z - jref, v1.z);  ROUTE16(c1.w - jref, v1.w);
        ROUTE16(c2.x - jref, v2.x);  ROUTE16(c2.y - jref, v2.y);
        ROUTE16(c2.z - jref, v2.z);  ROUTE16(c2.w - jref, v2.w);
        ROUTE16(c3.x - jref, v3.x);  ROUTE16(c3.y - jref, v3.y);
        ROUTE16(c3.z - jref, v3.z);  ROUTE16(c3.w - jref, v3.w);
    }

    const float4* __restrict__ x4 = (const float4*)x;
    const bool g0 = (unsigned)(vb + 0) < (unsigned)nv;
    const bool g1 = (unsigned)(vb + 1) < (unsigned)nv;
    const bool g2 = (unsigned)(vb + 2) < (unsigned)nv;
    const bool g3 = (unsigned)(vb + 3) < (unsigned)nv;
    const bool g4 = (unsigned)(vb + 4) < (unsigned)nv;
    const float4 Z = make_float4(0.f, 0.f, 0.f, 0.f);

    // ---- Per channel: 5 coalesced aligned LDG.128 + 16 FMAs + store ----
    #pragma unroll
    for (int c = 0; c < CCH; c++) {
        const float4* B = x4 + (size_t)c * nv + vb;
        float4 F0 = g0 ? B[0] : Z;
        float4 F1 = g1 ? B[1] : Z;
        float4 F2 = g2 ? B[2] : Z;
        float4 F3 = g3 ? B[3] : Z;
        float4 F4 = g4 ? B[4] : Z;

        // tap j multiplies window float (4k-8) + (j+2)
        float a0 = w0 * F0.z;
        float a1 = w1 * F0.w;
        a0 = fmaf(w2, F1.x, a0);  a1 = fmaf(w3, F1.y, a1);
        a0 = fmaf(w4, F1.z, a0);  a1 = fmaf(w5, F1.w, a1);
        a0 = fmaf(w6, F2.x, a0);  a1 = fmaf(w7, F2.y, a1);
        a0 = fmaf(w8, F2.z, a0);  a1 = fmaf(w9, F2.w, a1);
        a0 = fmaf(wA, F3.x, a0);  a1 = fmaf(wB, F3.y, a1);
        a0 = fmaf(wC, F3.z, a0);  a1 = fmaf(wD, F3.w, a1);
        a0 = fmaf(wE, F4.x, a0);  a1 = fmaf(wF, F4.y, a1);

        out[(size_t)c * k_out + k] = a0 + a1;
    }

    // ---- cell_ids pass-through (second tuple element) ----
    out[(size_t)CCH * k_out + k] = (float)cell_ids[k];
}

extern "C" void kernel_launch(void* const* d_in, const int* in_sizes, int n_in_args,
                              void* d_out, int out_size)
{
    const float* x        = (const float*)d_in[0];   // (1, 8, N_IN) f32
    const int*   M_cols   = (const int*)  d_in[1];   // (K_OUT, 16) i32
    const float* M_vals   = (const float*)d_in[2];   // (K_OUT, 16) f32
    const int*   cell_ids = (const int*)  d_in[3];   // (K_OUT,)    i32

    const int N_IN  = in_sizes[0] / CCH;      // 3,145,728
    const int K_OUT = in_sizes[3];            // 786,432

    float* out = (float*)d_out;

    const int grid = (K_OUT + KPB - 1) / KPB; // 3072, exact
    sphere_down_kernel<<<grid, KPB>>>(x, M_cols, M_vals, cell_ids, out,
                                      N_IN, K_OUT);
}